// round 3
// baseline (speedup 1.0000x reference)
#include <cuda_runtime.h>
#include <math.h>

// Reference reduces exactly to: out = 1.0 + gelu(bn(conv3x3_groups2(x4, local_w)))
// (softmax over the size-1 axis is identically 1; attn @ ones = 1.)

#define NPW 24
#define NPOS 576
#define ICG 64
#define OCB 8            // output channels per block
#define RB 3             // output rows per block
#define SROWS 5          // RB + 2 halo
#define THREADS 96       // 12 w-pairs x 8 oc
#define SMEM_X (ICG*SROWS*NPW)   // 7680 floats
#define SMEM_W (ICG*9*OCB)       // 4608 floats, [ic][k][oc]
#define SMEM_BYTES ((SMEM_X + SMEM_W)*4)   // 49152 bytes

__global__ __launch_bounds__(THREADS)
void fused_c_kernel(const float* __restrict__ x,    // (2, 128, 24, 24) flat
                    const float* __restrict__ lw,   // (128, 64, 3, 3)
                    const float* __restrict__ gma,
                    const float* __restrict__ bta,
                    float* __restrict__ out)        // (2, 128, 24, 24) flat
{
    extern __shared__ float sm[];
    float* sX = sm;            // [ic][r(5)][w(24)]
    float* sW = sm + SMEM_X;   // [ic][k(9)][o(8)]

    int bid = blockIdx.x;
    int ht  = bid & 7;  bid >>= 3;   // 8 row tiles of 3
    int occ = bid & 7;  bid >>= 3;   // 8 oc chunks of 8
    int g   = bid & 1;
    int b   = bid >> 1;

    const int h0 = ht * RB;
    const int ocBase = g * 64 + occ * OCB;
    const int tid = threadIdx.x;

    // ---- stage input rows h0-1 .. h0+3 (float4) ----
    const float* xb = x + b * (128 * NPOS) + (g * ICG) * NPOS;
    #pragma unroll 5
    for (int i4 = tid; i4 < ICG * SROWS * 6; i4 += THREADS) {   // 1920 float4
        int ic  = i4 / 30;
        int rem = i4 - ic * 30;
        int r   = rem / 6;
        int w4  = rem - r * 6;
        int h   = h0 - 1 + r;
        float4 v = make_float4(0.f, 0.f, 0.f, 0.f);
        if ((unsigned)h < 24u)
            v = *reinterpret_cast<const float4*>(xb + ic * NPOS + h * NPW + w4 * 4);
        reinterpret_cast<float4*>(sX)[i4] = v;
    }

    // ---- stage weights transposed to [ic][k][oc] ----
    const float* wb = lw + ocBase * (ICG * 9);
    #pragma unroll 8
    for (int i = tid; i < OCB * ICG * 9; i += THREADS) {
        int o   = i / (ICG * 9);
        int rem = i - o * (ICG * 9);
        int ic  = rem / 9;
        int k   = rem - ic * 9;
        sW[(ic * 9 + k) * OCB + o] = wb[i];
    }
    __syncthreads();

    // ---- compute: thread = (oc, w-pair), 3 output rows x 2 cols ----
    const int w2 = tid % 12;
    const int o  = tid / 12;        // 0..7
    const int w0 = w2 * 2;

    float acc0[RB], acc1[RB];
    #pragma unroll
    for (int r = 0; r < RB; r++) { acc0[r] = 0.f; acc1[r] = 0.f; }

    #pragma unroll 2
    for (int ic = 0; ic < ICG; ic++) {
        const float* wr = sW + ic * 9 * OCB + o;
        float wk[9];
        #pragma unroll
        for (int k = 0; k < 9; k++) wk[k] = wr[k * OCB];

        const float* xr = sX + ic * (SROWS * NPW) + w0;
        float xa[SROWS], xb0[SROWS], xb1[SROWS], xc[SROWS];
        #pragma unroll
        for (int r = 0; r < SROWS; r++) {
            const float* row = xr + r * NPW;
            float2 m = *reinterpret_cast<const float2*>(row);   // cols w0, w0+1
            xb0[r] = m.x;
            xb1[r] = m.y;
            xa[r]  = (w2 > 0)  ? row[-1] : 0.f;                 // col w0-1
            xc[r]  = (w2 < 11) ? row[2]  : 0.f;                 // col w0+2
        }

        #pragma unroll
        for (int r = 0; r < RB; r++) {
            #pragma unroll
            for (int kh = 0; kh < 3; kh++) {
                const int rr = r + kh;
                const float k0 = wk[kh * 3 + 0];
                const float k1 = wk[kh * 3 + 1];
                const float k2 = wk[kh * 3 + 2];
                acc0[r] += k0 * xa[rr];
                acc0[r] += k1 * xb0[rr];
                acc0[r] += k2 * xb1[rr];
                acc1[r] += k0 * xb0[rr];
                acc1[r] += k1 * xb1[rr];
                acc1[r] += k2 * xc[rr];
            }
        }
    }

    // ---- epilogue: BN affine + exact GELU + 1.0 ----
    const int oc = ocBase + o;
    const float ge = gma[oc] * 0.9999950000374997f;  // gamma / sqrt(1 + 1e-5)
    const float be = bta[oc];
    float* ob = out + b * (128 * NPOS) + oc * NPOS + h0 * NPW + w0;
    #pragma unroll
    for (int r = 0; r < RB; r++) {
        float y0 = acc0[r] * ge + be;
        float y1 = acc1[r] * ge + be;
        float g0 = 0.5f * y0 * (1.0f + erff(y0 * 0.70710678118654752f));
        float g1 = 0.5f * y1 * (1.0f + erff(y1 * 0.70710678118654752f));
        *reinterpret_cast<float2*>(ob + r * NPW) = make_float2(1.0f + g0, 1.0f + g1);
    }
}

extern "C" void kernel_launch(void* const* d_in, const int* in_sizes, int n_in,
                              void* d_out, int out_size)
{
    const float* x   = (const float*)d_in[0];
    const float* lw  = (const float*)d_in[9];   // local_w
    const float* gma = (const float*)d_in[10];  // bnc1_gamma
    const float* bta = (const float*)d_in[11];  // bnc1_beta
    float* out = (float*)d_out;

    cudaFuncSetAttribute(fused_c_kernel,
                         cudaFuncAttributeMaxDynamicSharedMemorySize, SMEM_BYTES);
    fused_c_kernel<<<256, THREADS, SMEM_BYTES>>>(x, lw, gma, bta, out);
}